// round 17
// baseline (speedup 1.0000x reference)
#include <cuda_runtime.h>
#include <cstddef>

// JPEG 8x8 blockify + orthonormal 2D DCT-II + QF quantization.
// image: [16,1,1024,1024] f32, qf: [16] f32 -> out [16,64,128,128] f32.
//
// R18 = R15 (best e2e 21.1us: persistent, register double-buffered
// prefetch, 2 threads per 8x8 block, evict-last L2-pinned input,
// __stcs streaming stores) restructured ROW-FIRST so each thread loads
// 4 complete 8-float rows with LDG.256:
//   ld.global.nc.L2::evict_last.v8.b32   (legal on sm_103a for .v8 only)
// -> half the load instructions, bare evict-last qualifier (no
// createpolicy). Thread h owns rows 4h..4h+3: row DCT is 4 local dct8;
// the column pass uses the proven pair-shuffle butterfly (DCT is
// transpose-symmetric, coefficients identical). Quant scales stored
// TRANSPOSED in smem (T[l*8+k]) so the epilogue keeps LDS.128.

#define A0 0.35355339059327373f  // 1/sqrt(8)
#define H1 0.49039264020161522f  // cos(1*pi/16)/2
#define H2 0.46193976625564337f  // cos(2*pi/16)/2
#define H3 0.41573480615127262f  // cos(3*pi/16)/2
#define H4 0.35355339059327376f  // cos(4*pi/16)/2
#define H5 0.27778511650980111f  // cos(5*pi/16)/2
#define H6 0.19134171618254489f  // cos(6*pi/16)/2
#define H7 0.09754516100806413f  // cos(7*pi/16)/2

#define NROWS 2048   // 16 images * 128 block-rows
#define GRID  296    // 2 CTAs/SM * 148 SMs

__constant__ float c_qtab[64] = {
    16.f, 11.f, 10.f, 16.f, 24.f, 40.f, 51.f, 61.f,
    12.f, 12.f, 14.f, 19.f, 26.f, 58.f, 60.f, 55.f,
    14.f, 13.f, 16.f, 24.f, 40.f, 57.f, 69.f, 56.f,
    14.f, 17.f, 22.f, 29.f, 51.f, 87.f, 80.f, 62.f,
    18.f, 22.f, 37.f, 56.f, 68.f, 109.f, 103.f, 77.f,
    24.f, 36.f, 55.f, 64.f, 81.f, 104.f, 113.f, 92.f,
    49.f, 64.f, 78.f, 87.f, 103.f, 121.f, 120.f, 101.f,
    72.f, 92.f, 95.f, 98.f, 112.f, 100.f, 103.f, 99.f};

// 256-bit load, read-only path, L2 evict-last (input pinned in L2).
__device__ __forceinline__ void ldg256_pin(const float* __restrict__ p,
                                           float* v) {
    asm("ld.global.nc.L2::evict_last.v8.b32 {%0,%1,%2,%3,%4,%5,%6,%7}, [%8];"
        : "=f"(v[0]), "=f"(v[1]), "=f"(v[2]), "=f"(v[3]),
          "=f"(v[4]), "=f"(v[5]), "=f"(v[6]), "=f"(v[7])
        : "l"(p));
}

__device__ __forceinline__ void dct8(float& x0, float& x1, float& x2, float& x3,
                                     float& x4, float& x5, float& x6, float& x7) {
    float e0 = x0 + x7, e1 = x1 + x6, e2 = x2 + x5, e3 = x3 + x4;
    float o0 = x0 - x7, o1 = x1 - x6, o2 = x2 - x5, o3 = x3 - x4;
    float ee0 = e0 + e3, ee1 = e1 + e2;
    float eo0 = e0 - e3, eo1 = e1 - e2;
    x0 = A0 * (ee0 + ee1);
    x4 = H4 * (ee0 - ee1);
    x2 = H2 * eo0 + H6 * eo1;
    x6 = H6 * eo0 - H2 * eo1;
    x1 = H1 * o0 + H3 * o1 + H5 * o2 + H7 * o3;
    x3 = H3 * o0 - H7 * o1 - H1 * o2 - H5 * o3;
    x5 = H5 * o0 - H1 * o1 + H7 * o2 + H3 * o3;
    x7 = H7 * o0 - H5 * o1 + H3 * o2 - H1 * o3;
}

struct Coef {
    float cA0, cA1, cB0, cB1;
    float cC0, cC1, cC2, cC3;
    float cD0, cD1, cD2, cD3;
    float dcfix;
};

// Thread h loads its 4 full rows (4h..4h+3) of block (row, wb): 4x LDG.256.
__device__ __forceinline__ void load_tile(const float* __restrict__ img,
                                          int row, int wb, int h,
                                          float x[4][8]) {
    int b = row >> 7;
    int hb = row & 127;
    const float* p = img + ((size_t)b << 20) + (size_t)hb * 8192
                     + (size_t)(h * 4) * 1024 + wb * 8;
#pragma unroll
    for (int r = 0; r < 4; r++) {
        ldg256_pin(p + (size_t)r * 1024, x[r]);
    }
}

__device__ __forceinline__ void process_tile(float x[4][8], int row, int wb,
                                             int h, const Coef& cf,
                                             const float* __restrict__ sScaleT,
                                             float* __restrict__ out) {
    int b = row >> 7;
    int hb = row & 127;

    // Row transform: 4 own rows, fully local.
#pragma unroll
    for (int r = 0; r < 4; r++) {
        dct8(x[r][0], x[r][1], x[r][2], x[r][3],
             x[r][4], x[r][5], x[r][6], x[r][7]);
    }

    // Column pass per l: pair-shuffle butterfly over the 8 rows (4 own +
    // 4 partner). Thread h emits row-freqs k = 4h+{0,1,2,3}.
    const float* scb = &sScaleT[b * 64 + 4 * h];
    // plane = k*8 + l; base plane for this thread = 32h.
    float* ob = out + ((size_t)b << 20) + (size_t)(h * 32) * 16384
                + hb * 128 + wb;

#pragma unroll
    for (int l = 0; l < 8; l++) {
        float v0 = x[0][l], v1 = x[1][l], v2 = x[2][l], v3 = x[3][l];
        float p0 = __shfl_xor_sync(0xffffffffu, v0, 1);
        float p1 = __shfl_xor_sync(0xffffffffu, v1, 1);
        float p2 = __shfl_xor_sync(0xffffffffu, v2, 1);
        float p3 = __shfl_xor_sync(0xffffffffu, v3, 1);
        // s_i = e_i (h=0) / e_{3-i} (h=1);  d_i = o_i (h=0) / -o_{3-i} (h=1)
        float s0 = v0 + p3, s1 = v1 + p2, s2 = v2 + p1, s3 = v3 + p0;
        float d0 = v0 - p3, d1 = v1 - p2, d2 = v2 - p1, d3 = v3 - p0;
        float ee0 = s0 + s3, ee1 = s1 + s2;
        float u0 = s0 - s3, u1 = s1 - s2;

        float oA = cf.cA0 * ee0 + cf.cA1 * ee1;                       // k = 4h+0
        if (l == 0) oA -= cf.dcfix;  // -128 input shift affects only (0,0)
        float oB = cf.cB0 * u0 + cf.cB1 * u1;                         // k = 4h+2
        float oC = cf.cC0 * d0 + cf.cC1 * d1 + cf.cC2 * d2 + cf.cC3 * d3;
        float oD = cf.cD0 * d0 + cf.cD1 * d1 + cf.cD2 * d2 + cf.cD3 * d3;

        // Transposed scales: sc.{x,y,z,w} = scale for k=4h+{0,1,2,3} at l.
        float4 sc = *(const float4*)&scb[l * 8];
        float* ok = ob + (size_t)l * 16384;
        __stcs(ok,                      oA * sc.x);   // k=4h+0
        __stcs(ok + (size_t)1 * 131072, oC * sc.y);   // k=4h+1 (+8 planes)
        __stcs(ok + (size_t)2 * 131072, oB * sc.z);   // k=4h+2
        __stcs(ok + (size_t)3 * 131072, oD * sc.w);   // k=4h+3
    }
}

__global__ __launch_bounds__(256, 2) void jpeg_dct_kernel(
    const float* __restrict__ img,
    const float* __restrict__ qf,
    float* __restrict__ out) {
    __shared__ __align__(16) float sScaleT[16 * 64];  // transposed: [b][l][k]

    // Precompute every image's 64 quant scales once (transposed layout).
    for (int i = threadIdx.x; i < 16 * 64; i += 256) {
        int bi = i >> 6;
        int idx = i & 63;
        int l = idx >> 3;
        int k = idx & 7;
        float q = qf[bi];
        float factor = (q < 50.0f) ? (5000.0f / q) : (200.0f - 2.0f * q);
        sScaleT[i] = 100.0f / (c_qtab[k * 8 + l] * factor);
    }
    __syncthreads();

    int wb = threadIdx.x >> 1;
    int h = threadIdx.x & 1;   // half: owns rows 4h..4h+3
    bool hi = (h != 0);

    Coef cf;
    cf.cA0 = hi ?  H4 :  A0;  cf.cA1 = hi ? -H4 :  A0;   // k0 / k4
    cf.cB0 = hi ? -H6 :  H2;  cf.cB1 = hi ?  H2 :  H6;   // k2 / k6
    cf.cC0 = hi ? -H3 :  H1;  cf.cC1 = hi ? -H7 :  H3;   // k1 / k5
    cf.cC2 = hi ?  H1 :  H5;  cf.cC3 = hi ? -H5 :  H7;
    cf.cD0 = hi ?  H1 :  H3;  cf.cD1 = hi ? -H3 : -H7;   // k3 / k7
    cf.cD2 = hi ?  H5 : -H1;  cf.cD3 = hi ? -H7 : -H5;
    cf.dcfix = hi ? 0.0f : 1024.0f;

    // Register double-buffered persistent loop: next tile's 4 LDG.256 are
    // issued before the current tile's compute+store phase.
    float xA[4][8], xB[4][8];
    int rA = blockIdx.x;
    load_tile(img, rA, wb, h, xA);
    while (rA < NROWS) {
        int rB = rA + GRID;
        if (rB < NROWS) load_tile(img, rB, wb, h, xB);
        process_tile(xA, rA, wb, h, cf, sScaleT, out);
        rA += 2 * GRID;
        if (rA < NROWS) load_tile(img, rA, wb, h, xA);
        if (rB < NROWS) process_tile(xB, rB, wb, h, cf, sScaleT, out);
    }
}

extern "C" void kernel_launch(void* const* d_in, const int* in_sizes, int n_in,
                              void* d_out, int out_size) {
    const float* img = (const float*)d_in[0];
    const float* qf = (const float*)d_in[1];
    float* out = (float*)d_out;
    jpeg_dct_kernel<<<GRID, 256>>>(img, qf, out);
}